// round 15
// baseline (speedup 1.0000x reference)
#include <cuda_runtime.h>
#include <cuda_fp16.h>
#include <cstdint>
#include <math.h>

// ---------------- problem constants ----------------
#define BB 2048
#define KK 2048
#define HH 2048
#define FH 8192

// ---------------- GEMM config: fp16 single product, wide warp tiles ---------
#define BM 64
#define BN 128             // 4 gates x 32 h
#define BK 128             // two 64-elem sub-blocks (128B rows)
#define NTH 128            // 4 warps: 2 (M, m32) x 2 (N, n64)
#define NCHUNK 32          // 2 phases * (2048/128)
#define ROWB 128
#define OFF_A1  8192
#define OFF_W0 16384
#define STAGE_BYTES 49152  // A 16K + W 32K
#define NSTAGE 2
#define SMEM_TOTAL (NSTAGE*STAGE_BYTES)   // 96 KB; 2 CTAs/SM
#define EPI_STRIDE 132

// ---------------- scratch ----------------
__device__ __align__(16) __half g_a[2][(size_t)BB*KK];   // x, h (fp16)
__device__ __align__(16) __half g_w[2][(size_t)FH*KK];   // Wih, Whh (fp16)

// ---------------- PTX helpers ----------------
__device__ __forceinline__ uint32_t smem_u32(const void* p) {
    return (uint32_t)__cvta_generic_to_shared(p);
}
__device__ __forceinline__ void cp16(uint32_t s, const void* g) {
    asm volatile("cp.async.cg.shared.global [%0], [%1], 16;"
                 :: "r"(s), "l"(__cvta_generic_to_global(g)) : "memory");
}
__device__ __forceinline__ void cp_commit() {
    asm volatile("cp.async.commit_group;" ::: "memory");
}
template <int N>
__device__ __forceinline__ void cp_wait() {
    asm volatile("cp.async.wait_group %0;" :: "n"(N) : "memory");
}
__device__ __forceinline__ void ldsm4(uint32_t* r, uint32_t a) {
    asm volatile("ldmatrix.sync.aligned.m8n8.x4.shared.b16 {%0,%1,%2,%3}, [%4];"
                 : "=r"(r[0]), "=r"(r[1]), "=r"(r[2]), "=r"(r[3]) : "r"(a));
}
__device__ __forceinline__ void mma16816(float* c, const uint32_t* a, const uint32_t* b) {
    asm volatile(
        "mma.sync.aligned.m16n8k16.row.col.f32.f16.f16.f32 "
        "{%0,%1,%2,%3}, {%4,%5,%6,%7}, {%8,%9}, {%0,%1,%2,%3};"
        : "+f"(c[0]), "+f"(c[1]), "+f"(c[2]), "+f"(c[3])
        : "r"(a[0]), "r"(a[1]), "r"(a[2]), "r"(a[3]), "r"(b[0]), "r"(b[1]));
}
__device__ __forceinline__ uint32_t swz(uint32_t x) {   // SW128
    return x ^ ((x >> 3) & 0x70);
}
__device__ __forceinline__ float sigmoidf_(float v) { return 1.0f / (1.0f + expf(-v)); }

// ---------------- one fused fp32 -> fp16 convert for all four tensors -------
#define CB_A 2048
#define CB_W 8192
__device__ __forceinline__ uint32_t packh2(float a, float b) {
    __half2 p(__float2half_rn(a), __float2half_rn(b));
    return *(uint32_t*)&p;
}
__global__ void convert_all(const float4* __restrict__ x,
                            const float4* __restrict__ h,
                            const float4* __restrict__ wih,
                            const float4* __restrict__ whh,
                            uint4* __restrict__ a16, uint4* __restrict__ w16)
{
    const int b = blockIdx.x;
    const float4* src;
    uint4* dst;
    int i;
    const int A8 = BB * KK / 8;
    const int W8 = FH * KK / 8;

    if (b < CB_A) {
        src = x;   dst = a16;        i = b * 256 + threadIdx.x;
        if (i >= A8) return;
    } else if (b < 2 * CB_A) {
        src = h;   dst = a16 + A8;   i = (b - CB_A) * 256 + threadIdx.x;
        if (i >= A8) return;
    } else if (b < 2 * CB_A + CB_W) {
        src = wih; dst = w16;        i = (b - 2 * CB_A) * 256 + threadIdx.x;
        if (i >= W8) return;
    } else {
        src = whh; dst = w16 + W8;   i = (b - 2 * CB_A - CB_W) * 256 + threadIdx.x;
        if (i >= W8) return;
    }

    float4 v0 = src[2 * i];
    float4 v1 = src[2 * i + 1];
    uint4 o;
    o.x = packh2(v0.x, v0.y);
    o.y = packh2(v0.z, v0.w);
    o.z = packh2(v1.x, v1.y);
    o.w = packh2(v1.z, v1.w);
    dst[i] = o;
}

// ---------------- tile loader: K128 chunk, sub-blocked 128B rows -------------
__device__ __forceinline__ void load_chunk(int c, uint32_t stage, int m0, int hb, int tid)
{
    const int ph = c >> 4;
    const int k0 = (c & 15) * BK;
    const __half* __restrict__ A = g_a[ph];
    const __half* __restrict__ W = g_w[ph];

    #pragma unroll
    for (int j = 0; j < 8; ++j) {          // A: 64 rows x 16 x 16B = 1024 items
        int idx = tid + j * NTH;
        int r = idx >> 4, cb = idx & 15;
        int blk = cb >> 3, w16 = cb & 7;
        uint32_t so = (uint32_t)blk * OFF_A1 + swz((uint32_t)(r * ROWB + w16 * 16));
        size_t go = (size_t)(m0 + r) * KK + k0 + blk * 64 + w16 * 8;
        cp16(stage + so, A + go);
    }
    #pragma unroll
    for (int j = 0; j < 16; ++j) {         // W: 128 rows x 16 x 16B = 2048 items
        int idx = tid + j * NTH;
        int r = idx >> 4, cb = idx & 15;
        int blk = cb >> 3, w16 = cb & 7;
        int wrow = ((r >> 5) << 11) + hb + (r & 31);   // gate*2048 + hb + h
        uint32_t so = OFF_W0 + (uint32_t)blk * 16384 +
                      swz((uint32_t)(r * ROWB + w16 * 16));
        size_t go = (size_t)wrow * KK + k0 + blk * 64 + w16 * 8;
        cp16(stage + so, W + go);
    }
}

// fragment fetch for one kstep: 4 B-ldsm + 2 A-ldsm
__device__ __forceinline__ void ld_frags(int ks, uint32_t base,
                                         const uint32_t* swzA, const uint32_t* swzB,
                                         uint32_t bfr[4][4], uint32_t afr[2][4])
{
    const uint32_t aBlk = base + (uint32_t)(ks >> 2) * OFF_A1;
    const uint32_t wBlk = base + OFF_W0 + (uint32_t)(ks >> 2) * 16384;
    const uint32_t kx = (uint32_t)(ks & 3) << 5;
    #pragma unroll
    for (int np = 0; np < 4; ++np)
        ldsm4(bfr[np], wBlk + (swzB[np] ^ kx));
    #pragma unroll
    for (int mt = 0; mt < 2; ++mt)
        ldsm4(afr[mt], aBlk + (swzA[mt] ^ kx));
}

// ---------------- single-product fp16 GEMM + fused LSTM epilogue ------------
// 4 warps, warp tile m32 x n64, kstep fragment double-buffering.
__global__ __launch_bounds__(NTH, 2)
void lstm_gemm_fused(const float* __restrict__ Cprev,
                     const float* __restrict__ bih,
                     const float* __restrict__ bhh,
                     float* __restrict__ out)
{
    extern __shared__ __align__(1024) char smem[];
    const uint32_t sb = smem_u32(smem);
    const int tid = threadIdx.x;
    const int wid = tid >> 5;
    const int l   = tid & 31;
    const int m0  = blockIdx.y * BM;
    const int hb  = blockIdx.x * 32;
    const int wm  = wid & 1;      // 32-row slab
    const int wn  = wid >> 1;     // 64-col slab

    float acc[2][8][4];
    #pragma unroll
    for (int mt = 0; mt < 2; ++mt)
        #pragma unroll
        for (int nt = 0; nt < 8; ++nt)
            #pragma unroll
            for (int q = 0; q < 4; ++q) acc[mt][nt][q] = 0.0f;

    uint32_t swzA[2];
    #pragma unroll
    for (int mt = 0; mt < 2; ++mt) {
        int r = wm * 32 + mt * 16 + (l & 15);
        swzA[mt] = swz((uint32_t)(r * ROWB + (l >> 4) * 16));
    }
    uint32_t swzB[4];
    #pragma unroll
    for (int np = 0; np < 4; ++np) {
        int r = wn * 64 + np * 16 + ((l >> 4) << 3) + (l & 7);
        swzB[np] = swz((uint32_t)(r * ROWB + ((l >> 3) & 1) * 16));
    }

    load_chunk(0, sb, m0, hb, tid);
    cp_commit();
    load_chunk(1, sb + STAGE_BYTES, m0, hb, tid);
    cp_commit();

    for (int c = 0; c < NCHUNK; ++c) {
        const uint32_t base = sb + (uint32_t)(c & 1) * STAGE_BYTES;

        cp_wait<1>();
        __syncthreads();

        uint32_t bfr[2][4][4], afr[2][2][4];
        ld_frags(0, base, swzA, swzB, bfr[0], afr[0]);

        #pragma unroll
        for (int ks = 0; ks < 8; ++ks) {
            const int cur = ks & 1;
            // Prefetch next kstep's fragments: ldsm latency overlaps MMAs.
            if (ks < 7)
                ld_frags(ks + 1, base, swzA, swzB, bfr[cur ^ 1], afr[cur ^ 1]);

            #pragma unroll
            for (int mt = 0; mt < 2; ++mt)
                #pragma unroll
                for (int nt = 0; nt < 8; ++nt)
                    mma16816(acc[mt][nt], afr[cur][mt],
                             &bfr[cur][nt >> 1][(nt & 1) * 2]);
        }

        __syncthreads();
        if (c + NSTAGE < NCHUNK)
            load_chunk(c + NSTAGE, base, m0, hb, tid);
        cp_commit();
    }

    // ---- fused epilogue ----
    __syncthreads();
    float* sg = (float*)smem;              // [64][EPI_STRIDE] f32 gate tile

    const int rb = wm * 32 + (l >> 2);
    const int cb = wn * 64 + 2 * (l & 3);
    #pragma unroll
    for (int mt = 0; mt < 2; ++mt) {
        #pragma unroll
        for (int nt = 0; nt < 8; ++nt) {
            const int r = rb + mt * 16;
            const int cc = cb + nt * 8;
            sg[r * EPI_STRIDE + cc]           = acc[mt][nt][0];
            sg[r * EPI_STRIDE + cc + 1]       = acc[mt][nt][1];
            sg[(r + 8) * EPI_STRIDE + cc]     = acc[mt][nt][2];
            sg[(r + 8) * EPI_STRIDE + cc + 1] = acc[mt][nt][3];
        }
    }
    __syncthreads();

    const int hh = (tid & 7) * 4;
    const int H = hb + hh;
    float4 bI, bF, bG, bO;
    {
        float4 a0 = *(const float4*)(bih + H);
        float4 a1 = *(const float4*)(bhh + H);
        bI = make_float4(a0.x + a1.x, a0.y + a1.y, a0.z + a1.z, a0.w + a1.w);
        a0 = *(const float4*)(bih + HH + H);
        a1 = *(const float4*)(bhh + HH + H);
        bF = make_float4(a0.x + a1.x, a0.y + a1.y, a0.z + a1.z, a0.w + a1.w);
        a0 = *(const float4*)(bih + 2 * HH + H);
        a1 = *(const float4*)(bhh + 2 * HH + H);
        bG = make_float4(a0.x + a1.x, a0.y + a1.y, a0.z + a1.z, a0.w + a1.w);
        a0 = *(const float4*)(bih + 3 * HH + H);
        a1 = *(const float4*)(bhh + 3 * HH + H);
        bO = make_float4(a0.x + a1.x, a0.y + a1.y, a0.z + a1.z, a0.w + a1.w);
    }
    const size_t S = (size_t)BB * HH;

    for (int mr = tid >> 3; mr < BM; mr += 16) {
        const float* row = sg + mr * EPI_STRIDE;
        float4 gi = *(const float4*)(row + hh);
        float4 gf = *(const float4*)(row + 32 + hh);
        float4 gg = *(const float4*)(row + 64 + hh);
        float4 go = *(const float4*)(row + 96 + hh);
        const size_t gidx = (size_t)(m0 + mr) * HH + H;
        float4 C = *(const float4*)(Cprev + gidx);

        float4 vh, vC, vf, vi, vg, vo;
        const float* pgi = &gi.x; const float* pgf = &gf.x;
        const float* pgg = &gg.x; const float* pgo = &go.x;
        const float* pbI = &bI.x; const float* pbF = &bF.x;
        const float* pbG = &bG.x; const float* pbO = &bO.x;
        const float* pC = &C.x;
        float* ph = &vh.x; float* pc = &vC.x; float* pf = &vf.x;
        float* pi = &vi.x; float* pg = &vg.x; float* po = &vo.x;
        #pragma unroll
        for (int q = 0; q < 4; ++q) {
            float ig = sigmoidf_(pgi[q] + pbI[q]);
            float fg = sigmoidf_(pgf[q] + pbF[q]);
            float cg = tanhf(pgg[q] + pbG[q]);
            float og = sigmoidf_(pgo[q] + pbO[q]);
            float nC = fg * pC[q] + ig * cg;
            pf[q] = fg; pi[q] = ig; pg[q] = cg; po[q] = og;
            pc[q] = nC;
            ph[q] = og * tanhf(nC);
        }
        *(float4*)(out + gidx)         = vh;
        *(float4*)(out + S + gidx)     = vC;
        *(float4*)(out + 2 * S + gidx) = vf;
        *(float4*)(out + 3 * S + gidx) = vi;
        *(float4*)(out + 4 * S + gidx) = vg;
        *(float4*)(out + 5 * S + gidx) = vo;
    }
}

// ---------------- launch ----------------
extern "C" void kernel_launch(void* const* d_in, const int* in_sizes, int n_in,
                              void* d_out, int out_size)
{
    const float* x     = (const float*)d_in[0];
    const float* hprev = (const float*)d_in[1];
    const float* Cprev = (const float*)d_in[2];
    const float* Wih   = (const float*)d_in[3];
    const float* bih   = (const float*)d_in[4];
    const float* Whh   = (const float*)d_in[5];
    const float* bhh   = (const float*)d_in[6];
    float* out = (float*)d_out;

    __half *a16, *w16;
    cudaGetSymbolAddress((void**)&a16, g_a);
    cudaGetSymbolAddress((void**)&w16, g_w);

    static bool attr_set = false;
    if (!attr_set) {
        cudaFuncSetAttribute(lstm_gemm_fused,
                             cudaFuncAttributeMaxDynamicSharedMemorySize, SMEM_TOTAL);
        attr_set = true;
    }

    convert_all<<<2 * CB_A + 2 * CB_W, 256>>>(
        (const float4*)x, (const float4*)hprev,
        (const float4*)Wih, (const float4*)Whh,
        (uint4*)a16, (uint4*)w16);

    dim3 grid(FH / BN, BB / BM);   // (64, 32)
    lstm_gemm_fused<<<grid, NTH, SMEM_TOTAL>>>(Cprev, bih, bhh, out);
}

// round 16
// speedup vs baseline: 1.0046x; 1.0046x over previous
#include <cuda_runtime.h>
#include <cuda_fp16.h>
#include <cstdint>
#include <math.h>

// ---------------- problem constants ----------------
#define BB 2048
#define KK 2048
#define HH 2048
#define FH 8192

// ---------------- GEMM config: fp16 single product, wide warp tiles ---------
#define BM 64
#define BN 128             // 4 gates x 32 h
#define BK 128             // two 64-elem sub-blocks (128B rows)
#define NTH 128            // 4 warps: 2 (M, m32) x 2 (N, n64)
#define NCHUNK 32          // 2 phases * (2048/128)
#define ROWB 128
#define OFF_A1  8192
#define OFF_W0 16384
#define STAGE_BYTES 49152  // A 16K + W 32K
#define NSTAGE 2
#define SMEM_TOTAL (NSTAGE*STAGE_BYTES)   // 96 KB; 2 CTAs/SM
#define EPI_STRIDE 132

// ---------------- scratch ----------------
__device__ __align__(16) __half g_a[2][(size_t)BB*KK];   // x, h (fp16)
__device__ __align__(16) __half g_w[2][(size_t)FH*KK];   // Wih, Whh (fp16)

// ---------------- PTX helpers ----------------
__device__ __forceinline__ uint32_t smem_u32(const void* p) {
    return (uint32_t)__cvta_generic_to_shared(p);
}
__device__ __forceinline__ void cp16(uint32_t s, const void* g) {
    asm volatile("cp.async.cg.shared.global [%0], [%1], 16;"
                 :: "r"(s), "l"(__cvta_generic_to_global(g)) : "memory");
}
__device__ __forceinline__ void cp_commit() {
    asm volatile("cp.async.commit_group;" ::: "memory");
}
template <int N>
__device__ __forceinline__ void cp_wait() {
    asm volatile("cp.async.wait_group %0;" :: "n"(N) : "memory");
}
__device__ __forceinline__ void ldsm4(uint32_t* r, uint32_t a) {
    asm volatile("ldmatrix.sync.aligned.m8n8.x4.shared.b16 {%0,%1,%2,%3}, [%4];"
                 : "=r"(r[0]), "=r"(r[1]), "=r"(r[2]), "=r"(r[3]) : "r"(a));
}
__device__ __forceinline__ void mma16816(float* c, const uint32_t* a, const uint32_t* b) {
    asm volatile(
        "mma.sync.aligned.m16n8k16.row.col.f32.f16.f16.f32 "
        "{%0,%1,%2,%3}, {%4,%5,%6,%7}, {%8,%9}, {%0,%1,%2,%3};"
        : "+f"(c[0]), "+f"(c[1]), "+f"(c[2]), "+f"(c[3])
        : "r"(a[0]), "r"(a[1]), "r"(a[2]), "r"(a[3]), "r"(b[0]), "r"(b[1]));
}
__device__ __forceinline__ uint32_t swz(uint32_t x) {   // SW128
    return x ^ ((x >> 3) & 0x70);
}
__device__ __forceinline__ float sigmoidf_(float v) { return 1.0f / (1.0f + expf(-v)); }

// ---------------- fused fp32 -> fp16 convert, MLP=4 -------------------------
// Each thread handles uint4 slots i and i+half (4 independent LDG.128).
#define CB_A 1024
#define CB_W 4096
__device__ __forceinline__ uint32_t packh2(float a, float b) {
    __half2 p(__float2half_rn(a), __float2half_rn(b));
    return *(uint32_t*)&p;
}
__global__ void convert_all(const float4* __restrict__ x,
                            const float4* __restrict__ h,
                            const float4* __restrict__ wih,
                            const float4* __restrict__ whh,
                            uint4* __restrict__ a16, uint4* __restrict__ w16)
{
    const int b = blockIdx.x;
    const float4* src;
    uint4* dst;
    int i, half;
    const int A8 = BB * KK / 8;
    const int W8 = FH * KK / 8;

    if (b < CB_A) {
        src = x;   dst = a16;       half = A8 >> 1;
        i = b * 256 + threadIdx.x;            if (i >= half) return;
    } else if (b < 2 * CB_A) {
        src = h;   dst = a16 + A8;  half = A8 >> 1;
        i = (b - CB_A) * 256 + threadIdx.x;   if (i >= half) return;
    } else if (b < 2 * CB_A + CB_W) {
        src = wih; dst = w16;       half = W8 >> 1;
        i = (b - 2 * CB_A) * 256 + threadIdx.x;        if (i >= half) return;
    } else {
        src = whh; dst = w16 + W8;  half = W8 >> 1;
        i = (b - 2 * CB_A - CB_W) * 256 + threadIdx.x; if (i >= half) return;
    }
    const int j = i + half;

    // 4 independent 16B loads in flight
    float4 v0 = src[2 * i];
    float4 v1 = src[2 * i + 1];
    float4 v2 = src[2 * j];
    float4 v3 = src[2 * j + 1];

    uint4 o;
    o.x = packh2(v0.x, v0.y);
    o.y = packh2(v0.z, v0.w);
    o.z = packh2(v1.x, v1.y);
    o.w = packh2(v1.z, v1.w);
    dst[i] = o;
    o.x = packh2(v2.x, v2.y);
    o.y = packh2(v2.z, v2.w);
    o.z = packh2(v3.x, v3.y);
    o.w = packh2(v3.z, v3.w);
    dst[j] = o;
}

// ---------------- tile loader: K128 chunk, sub-blocked 128B rows -------------
// stage: [A k0-63 8K][A k64-127 8K][W k0-63 16K][W k64-127 16K]
__device__ __forceinline__ void load_chunk(int c, uint32_t stage, int m0, int hb, int tid)
{
    const int ph = c >> 4;
    const int k0 = (c & 15) * BK;
    const __half* __restrict__ A = g_a[ph];
    const __half* __restrict__ W = g_w[ph];

    #pragma unroll
    for (int j = 0; j < 8; ++j) {          // A: 64 rows x 16 x 16B = 1024 items
        int idx = tid + j * NTH;
        int r = idx >> 4, cb = idx & 15;
        int blk = cb >> 3, w16 = cb & 7;
        uint32_t so = (uint32_t)blk * OFF_A1 + swz((uint32_t)(r * ROWB + w16 * 16));
        size_t go = (size_t)(m0 + r) * KK + k0 + blk * 64 + w16 * 8;
        cp16(stage + so, A + go);
    }
    #pragma unroll
    for (int j = 0; j < 16; ++j) {         // W: 128 rows x 16 x 16B = 2048 items
        int idx = tid + j * NTH;
        int r = idx >> 4, cb = idx & 15;
        int blk = cb >> 3, w16 = cb & 7;
        int wrow = ((r >> 5) << 11) + hb + (r & 31);   // gate*2048 + hb + h
        uint32_t so = OFF_W0 + (uint32_t)blk * 16384 +
                      swz((uint32_t)(r * ROWB + w16 * 16));
        size_t go = (size_t)wrow * KK + k0 + blk * 64 + w16 * 8;
        cp16(stage + so, W + go);
    }
}

// ---------------- single-product fp16 GEMM + fused LSTM epilogue ------------
// 4 warps, warp tile m32 x n64 (R14 structure — the measured best).
__global__ __launch_bounds__(NTH, 2)
void lstm_gemm_fused(const float* __restrict__ Cprev,
                     const float* __restrict__ bih,
                     const float* __restrict__ bhh,
                     float* __restrict__ out)
{
    extern __shared__ __align__(1024) char smem[];
    const uint32_t sb = smem_u32(smem);
    const int tid = threadIdx.x;
    const int wid = tid >> 5;
    const int l   = tid & 31;
    const int m0  = blockIdx.y * BM;
    const int hb  = blockIdx.x * 32;
    const int wm  = wid & 1;      // 32-row slab
    const int wn  = wid >> 1;     // 64-col slab

    float acc[2][8][4];
    #pragma unroll
    for (int mt = 0; mt < 2; ++mt)
        #pragma unroll
        for (int nt = 0; nt < 8; ++nt)
            #pragma unroll
            for (int q = 0; q < 4; ++q) acc[mt][nt][q] = 0.0f;

    uint32_t swzA[2];
    #pragma unroll
    for (int mt = 0; mt < 2; ++mt) {
        int r = wm * 32 + mt * 16 + (l & 15);
        swzA[mt] = swz((uint32_t)(r * ROWB + (l >> 4) * 16));
    }
    uint32_t swzB[4];
    #pragma unroll
    for (int np = 0; np < 4; ++np) {
        int r = wn * 64 + np * 16 + ((l >> 4) << 3) + (l & 7);
        swzB[np] = swz((uint32_t)(r * ROWB + ((l >> 3) & 1) * 16));
    }

    load_chunk(0, sb, m0, hb, tid);
    cp_commit();
    load_chunk(1, sb + STAGE_BYTES, m0, hb, tid);
    cp_commit();

    for (int c = 0; c < NCHUNK; ++c) {
        const uint32_t base = sb + (uint32_t)(c & 1) * STAGE_BYTES;

        cp_wait<1>();
        __syncthreads();

        #pragma unroll
        for (int ks = 0; ks < 8; ++ks) {
            const uint32_t aBlk = base + (uint32_t)(ks >> 2) * OFF_A1;
            const uint32_t wBlk = base + OFF_W0 + (uint32_t)(ks >> 2) * 16384;
            const uint32_t kx = (uint32_t)(ks & 3) << 5;

            uint32_t bfr[4][4];
            #pragma unroll
            for (int np = 0; np < 4; ++np)
                ldsm4(bfr[np], wBlk + (swzB[np] ^ kx));
            uint32_t afr[2][4];
            #pragma unroll
            for (int mt = 0; mt < 2; ++mt)
                ldsm4(afr[mt], aBlk + (swzA[mt] ^ kx));

            #pragma unroll
            for (int mt = 0; mt < 2; ++mt)
                #pragma unroll
                for (int nt = 0; nt < 8; ++nt)
                    mma16816(acc[mt][nt], afr[mt], &bfr[nt >> 1][(nt & 1) * 2]);
        }

        __syncthreads();
        if (c + NSTAGE < NCHUNK)
            load_chunk(c + NSTAGE, base, m0, hb, tid);
        cp_commit();
    }

    // ---- fused epilogue ----
    __syncthreads();
    float* sg = (float*)smem;              // [64][EPI_STRIDE] f32 gate tile

    const int rb = wm * 32 + (l >> 2);
    const int cb = wn * 64 + 2 * (l & 3);
    #pragma unroll
    for (int mt = 0; mt < 2; ++mt) {
        #pragma unroll
        for (int nt = 0; nt < 8; ++nt) {
            const int r = rb + mt * 16;
            const int cc = cb + nt * 8;
            sg[r * EPI_STRIDE + cc]           = acc[mt][nt][0];
            sg[r * EPI_STRIDE + cc + 1]       = acc[mt][nt][1];
            sg[(r + 8) * EPI_STRIDE + cc]     = acc[mt][nt][2];
            sg[(r + 8) * EPI_STRIDE + cc + 1] = acc[mt][nt][3];
        }
    }
    __syncthreads();

    const int hh = (tid & 7) * 4;
    const int H = hb + hh;
    float4 bI, bF, bG, bO;
    {
        float4 a0 = *(const float4*)(bih + H);
        float4 a1 = *(const float4*)(bhh + H);
        bI = make_float4(a0.x + a1.x, a0.y + a1.y, a0.z + a1.z, a0.w + a1.w);
        a0 = *(const float4*)(bih + HH + H);
        a1 = *(const float4*)(bhh + HH + H);
        bF = make_float4(a0.x + a1.x, a0.y + a1.y, a0.z + a1.z, a0.w + a1.w);
        a0 = *(const float4*)(bih + 2 * HH + H);
        a1 = *(const float4*)(bhh + 2 * HH + H);
        bG = make_float4(a0.x + a1.x, a0.y + a1.y, a0.z + a1.z, a0.w + a1.w);
        a0 = *(const float4*)(bih + 3 * HH + H);
        a1 = *(const float4*)(bhh + 3 * HH + H);
        bO = make_float4(a0.x + a1.x, a0.y + a1.y, a0.z + a1.z, a0.w + a1.w);
    }
    const size_t S = (size_t)BB * HH;

    // Hoisted output bases: one pointer add per stream, IMADs out of the loop.
    float* o_h = out + (size_t)m0 * HH + H;
    float* o_C = o_h + S;
    float* o_f = o_h + 2 * S;
    float* o_i = o_h + 3 * S;
    float* o_g = o_h + 4 * S;
    float* o_o = o_h + 5 * S;
    const float* pCb = Cprev + (size_t)m0 * HH + H;

    for (int mr = tid >> 3; mr < BM; mr += 16) {
        const float* row = sg + mr * EPI_STRIDE;
        float4 gi = *(const float4*)(row + hh);
        float4 gf = *(const float4*)(row + 32 + hh);
        float4 gg = *(const float4*)(row + 64 + hh);
        float4 go = *(const float4*)(row + 96 + hh);
        const size_t roff = (size_t)mr * HH;
        float4 C = *(const float4*)(pCb + roff);

        float4 vh, vC, vf, vi, vg, vo;
        const float* pgi = &gi.x; const float* pgf = &gf.x;
        const float* pgg = &gg.x; const float* pgo = &go.x;
        const float* pbI = &bI.x; const float* pbF = &bF.x;
        const float* pbG = &bG.x; const float* pbO = &bO.x;
        const float* pC = &C.x;
        float* ph = &vh.x; float* pc = &vC.x; float* pf = &vf.x;
        float* pi = &vi.x; float* pg = &vg.x; float* po = &vo.x;
        #pragma unroll
        for (int q = 0; q < 4; ++q) {
            float ig = sigmoidf_(pgi[q] + pbI[q]);
            float fg = sigmoidf_(pgf[q] + pbF[q]);
            float cg = tanhf(pgg[q] + pbG[q]);
            float og = sigmoidf_(pgo[q] + pbO[q]);
            float nC = fg * pC[q] + ig * cg;
            pf[q] = fg; pi[q] = ig; pg[q] = cg; po[q] = og;
            pc[q] = nC;
            ph[q] = og * tanhf(nC);
        }
        *(float4*)(o_h + roff) = vh;
        *(float4*)(o_C + roff) = vC;
        *(float4*)(o_f + roff) = vf;
        *(float4*)(o_i + roff) = vi;
        *(float4*)(o_g + roff) = vg;
        *(float4*)(o_o + roff) = vo;
    }
}

// ---------------- launch ----------------
extern "C" void kernel_launch(void* const* d_in, const int* in_sizes, int n_in,
                              void* d_out, int out_size)
{
    const float* x     = (const float*)d_in[0];
    const float* hprev = (const float*)d_in[1];
    const float* Cprev = (const float*)d_in[2];
    const float* Wih   = (const float*)d_in[3];
    const float* bih   = (const float*)d_in[4];
    const float* Whh   = (const float*)d_in[5];
    const float* bhh   = (const float*)d_in[6];
    float* out = (float*)d_out;

    __half *a16, *w16;
    cudaGetSymbolAddress((void**)&a16, g_a);
    cudaGetSymbolAddress((void**)&w16, g_w);

    static bool attr_set = false;
    if (!attr_set) {
        cudaFuncSetAttribute(lstm_gemm_fused,
                             cudaFuncAttributeMaxDynamicSharedMemorySize, SMEM_TOTAL);
        attr_set = true;
    }

    convert_all<<<2 * CB_A + 2 * CB_W, 256>>>(
        (const float4*)x, (const float4*)hprev,
        (const float4*)Wih, (const float4*)Whh,
        (uint4*)a16, (uint4*)w16);

    dim3 grid(FH / BN, BB / BM);   // (64, 32)
    lstm_gemm_fused<<<grid, NTH, SMEM_TOTAL>>>(Cprev, bih, bhh, out);
}